// round 9
// baseline (speedup 1.0000x reference)
#include <cuda_runtime.h>
#include <cuda_fp16.h>
#include <cstdint>

#define Hh 128
#define Ww 128
#define LL 16384          // H*W
#define NB 2
#define NC1 64
#define NC2 128
#define OUT_LV2_ELEMS 4194304
#define SENT 16384        // sentinel tap offset -> zero slot

// Scratch
__device__ unsigned short g_tab[NB * 9 * LL];                  // 576 KB tap offsets
__device__ uint2          g_blkh[(size_t)NB * (LL + 1) * 64];  // 16.8 MB half4 blocks

// ---------------------------------------------------------------------------
// k_tab: tap-offset table straight from hw (dtype sniff inline) + sentinel
// zeroing of g_blkh. 32 blocks, ~2us.
// ---------------------------------------------------------------------------
__global__ void k_tab(const int* __restrict__ hw) {
    __shared__ int s_or;
    int tid = threadIdx.x;
    if (tid == 0) s_or = 0;
    __syncthreads();
    int acc = 0;
#pragma unroll
    for (int k = 0; k < 8; k++) acc |= hw[2 * (tid + (k << 8)) + 1];
    if (acc) atomicOr(&s_or, 1);
    __syncthreads();
    int stride = s_or ? 1 : 2;                // int32 vs int64 source

    if (blockIdx.x == 0 && tid < 128) {       // zero sentinel cells
        int b = tid >> 6, c = tid & 63;
        g_blkh[((size_t)b * (LL + 1) + LL) * 64 + c] = make_uint2(0u, 0u);
    }

#pragma unroll
    for (int k = 0; k < 4; k++) {
        int gp = (blockIdx.x << 10) + (k << 8) + tid;   // 0..32767
        int b  = gp >> 14;
        int p  = gp & (LL - 1);
        int y = p >> 7, x = p & 127;
        unsigned short* tp = g_tab + (size_t)b * 9 * LL;
#pragma unroll
        for (int dy = -1; dy <= 1; dy++) {
#pragma unroll
            for (int dx = -1; dx <= 1; dx++) {
                int tap = (dy + 1) * 3 + (dx + 1);
                int oy = y - dy, ox = x - dx;
                unsigned short off = SENT;
                if ((unsigned)oy < Hh && (unsigned)ox < Ww) {
                    int m  = hw[((b << 14) + (oy << 7) + ox) * stride];
                    int sr = (m >> 7)  + dy;
                    int sc = (m & 127) + dx;
                    if ((unsigned)sr < Hh && (unsigned)sc < Ww)
                        off = (unsigned short)((sr << 7) + sc);
                }
                tp[tap * LL + p] = off;
            }
        }
    }
}

// ---------------------------------------------------------------------------
// k_blk: space-to-depth fp16 transpose of lv1 -> g_blkh (DRAM-streaming).
// ---------------------------------------------------------------------------
__global__ void k_blk(const float* __restrict__ lv1) {
    __shared__ uint2 s2h[64 * 33];
    unsigned* sw = (unsigned*)s2h;
    int bid = blockIdx.x;                     // 1024
    int tid = threadIdx.x;
    int vt = bid & 3;
    int mh = (bid >> 2) & 127;
    int b  = bid >> 9;
    int v0 = vt << 5;

#pragma unroll
    for (int k = 0; k < 8; k++) {
        int j  = tid + (k << 8);
        int c  = j >> 5;
        int dy = (j >> 4) & 1;
        int x4 = j & 15;
        const float4 val = *(const float4*)(lv1 + (((size_t)(b * NC1 + c)) << 16)
                                            + ((2 * mh + dy) << 8) + (v0 << 1) + (x4 << 2));
        int vl0 = x4 << 1;
        __half2 h0 = __floats2half2_rn(val.x, val.y);
        __half2 h1 = __floats2half2_rn(val.z, val.w);
        sw[(c * 33 + vl0    ) * 2 + dy] = *(unsigned*)&h0;
        sw[(c * 33 + vl0 + 1) * 2 + dy] = *(unsigned*)&h1;
    }
    __syncthreads();

    uint2* dst = g_blkh + ((size_t)b * (LL + 1) + (mh << 7) + v0) * 64;
#pragma unroll
    for (int k = 0; k < 8; k++) {
        int j  = tid + (k << 8);
        int vl = j >> 6;
        int c  = j & 63;
        dst[(size_t)vl * 64 + c] = s2h[c * 33 + vl];
    }
}

// ---------------------------------------------------------------------------
// k_lv2: plane-resident SMEM gather, 2 channels packed half2, 1024 threads.
// ---------------------------------------------------------------------------
__global__ void k_lv2(const float* __restrict__ lv2, float* __restrict__ out) {
    extern __shared__ unsigned s_plane[];            // 16385 half2
    int bcp = blockIdx.x;
    int cp  = bcp & 63;
    int b   = bcp >> 6;
    const float* base0 = lv2 + ((size_t)(b * NC2 + cp * 2) << 14);
    for (int i = threadIdx.x; i < LL; i += blockDim.x) {
        __half2 h = __floats2half2_rn(base0[i], base0[i + LL]);
        s_plane[i] = *(unsigned*)&h;
    }
    if (threadIdx.x == 0) s_plane[SENT] = 0u;
    __syncthreads();

    const unsigned short* tb = g_tab + (size_t)b * 9 * LL;
    float* out0 = out + ((size_t)(b * NC2 + cp * 2) << 14);
    const float inv9 = 1.0f / 9.0f;

#pragma unroll
    for (int it = 0; it < 8; it++) {
        int p1 = threadIdx.x + (it << 11);
        int p2 = p1 + 1024;
        float a0 = 0.f, a1 = 0.f, b0 = 0.f, b1 = 0.f;
#pragma unroll
        for (int tap = 0; tap < 9; tap++) {
            unsigned hv  = s_plane[tb[tap * LL + p1]];
            unsigned hw2 = s_plane[tb[tap * LL + p2]];
            float2 v = __half22float2(*(__half2*)&hv);
            float2 w = __half22float2(*(__half2*)&hw2);
            a0 += v.x; a1 += v.y;
            b0 += w.x; b1 += w.y;
        }
        out0[p1]      = a0 * inv9;
        out0[p1 + LL] = a1 * inv9;
        out0[p2]      = b0 * inv9;
        out0[p2 + LL] = b1 * inv9;
    }
}

// ---------------------------------------------------------------------------
// k_lv1: warp-per-cell gather; lane = 2 channels (uint4/tap). Taps loaded in
// groups of 5+4 (lower reg pressure -> 4 blocks/SM); output staged as half2
// (33.3KB smem), copied out as coalesced fp32 float2 stores.
// ---------------------------------------------------------------------------
__global__ void __launch_bounds__(256, 4) k_lv1(float* __restrict__ out) {
    extern __shared__ __half2 shh[];          // 128 rows x 65 half2 = 33280 B
    int bid  = blockIdx.x;                    // 2*128*2 = 512
    int vt   = bid & 1;
    int u    = (bid >> 1) & 127;
    int b    = bid >> 8;
    int v0   = vt << 6;
    int w    = threadIdx.x >> 5;
    int lane = threadIdx.x & 31;
    const unsigned short* tb = g_tab + (size_t)b * 9 * LL;
    const uint4* blkb = (const uint4*)g_blkh + ((size_t)b * (LL + 1)) * 32 + lane;
    const float inv9 = 1.0f / 9.0f;

#pragma unroll
    for (int jj = 0; jj < 8; jj++) {
        int j = (w << 3) + jj;                // local cell 0..63
        int cell = (u << 7) + v0 + j;
        float4 A0 = make_float4(0.f, 0.f, 0.f, 0.f);   // channel 2*lane
        float4 A1 = make_float4(0.f, 0.f, 0.f, 0.f);   // channel 2*lane+1
        {   // taps 0..4
            uint4 t[5];
#pragma unroll
            for (int tap = 0; tap < 5; tap++)
                t[tap] = blkb[((size_t)tb[tap * LL + cell]) << 5];
#pragma unroll
            for (int tap = 0; tap < 5; tap++) {
                float2 f0 = __half22float2(*(__half2*)&t[tap].x);
                float2 f1 = __half22float2(*(__half2*)&t[tap].y);
                float2 f2 = __half22float2(*(__half2*)&t[tap].z);
                float2 f3 = __half22float2(*(__half2*)&t[tap].w);
                A0.x += f0.x; A0.y += f0.y; A0.z += f1.x; A0.w += f1.y;
                A1.x += f2.x; A1.y += f2.y; A1.z += f3.x; A1.w += f3.y;
            }
        }
        {   // taps 5..8
            uint4 t[4];
#pragma unroll
            for (int tap = 0; tap < 4; tap++)
                t[tap] = blkb[((size_t)tb[(5 + tap) * LL + cell]) << 5];
#pragma unroll
            for (int tap = 0; tap < 4; tap++) {
                float2 f0 = __half22float2(*(__half2*)&t[tap].x);
                float2 f1 = __half22float2(*(__half2*)&t[tap].y);
                float2 f2 = __half22float2(*(__half2*)&t[tap].z);
                float2 f3 = __half22float2(*(__half2*)&t[tap].w);
                A0.x += f0.x; A0.y += f0.y; A0.z += f1.x; A0.w += f1.y;
                A1.x += f2.x; A1.y += f2.y; A1.z += f3.x; A1.w += f3.y;
            }
        }
        int c0 = lane << 1;
        shh[(c0     ) * 65 + j] = __floats2half2_rn(A0.x * inv9, A0.y * inv9); // py0 c0
        shh[(64 + c0) * 65 + j] = __floats2half2_rn(A0.z * inv9, A0.w * inv9); // py1 c0
        shh[(c0 + 1 ) * 65 + j] = __floats2half2_rn(A1.x * inv9, A1.y * inv9); // py0 c0+1
        shh[(65 + c0) * 65 + j] = __floats2half2_rn(A1.z * inv9, A1.w * inv9); // py1 c0+1
    }
    __syncthreads();

    // Copy-out: warp per row (128 rows), convert half2->float2, coalesced
    // 256B global stores.
    for (int r = w; r < 128; r += 8) {
        int py = r >> 6;
        int c  = r & 63;
        float2* orow = (float2*)(out + (((size_t)(b * NC1 + c)) << 16)
                                 + ((2 * u + py) << 8) + (v0 << 1));
        const __half2* srow = shh + r * 65;
        orow[lane]      = __half22float2(srow[lane]);
        orow[lane + 32] = __half22float2(srow[lane + 32]);
    }
}

// ---------------------------------------------------------------------------
// Launch DAG (fork/join, capture-legal):
//   stream0: evFork -> k_tab -> evTab -> k_lv2 -> (wait evDone)
//   s2:      (wait evFork) -> k_blk -> (wait evTab) -> k_lv1 -> evDone
// ---------------------------------------------------------------------------
extern "C" void kernel_launch(void* const* d_in, const int* in_sizes, int n_in,
                              void* d_out, int out_size) {
    const float* lv1 = nullptr;   // 8388608
    const float* lv2 = nullptr;   // 4194304
    const int*   hix = nullptr;   // 32768
    for (int i = 0; i < n_in; i++) {
        if (in_sizes[i] == 8388608)      lv1 = (const float*)d_in[i];
        else if (in_sizes[i] == 4194304) lv2 = (const float*)d_in[i];
        else if (in_sizes[i] == 32768)   hix = (const int*)d_in[i];
    }
    float* out = (float*)d_out;

    static cudaStream_t s2 = nullptr;
    static cudaEvent_t evFork = nullptr, evTab = nullptr, evDone = nullptr;
    if (!s2) {
        cudaStreamCreateWithFlags(&s2, cudaStreamNonBlocking);
        cudaEventCreateWithFlags(&evFork, cudaEventDisableTiming);
        cudaEventCreateWithFlags(&evTab,  cudaEventDisableTiming);
        cudaEventCreateWithFlags(&evDone, cudaEventDisableTiming);
        cudaFuncSetAttribute(k_lv2, cudaFuncAttributeMaxDynamicSharedMemorySize, 65544);
        cudaFuncSetAttribute(k_lv1, cudaFuncAttributeMaxDynamicSharedMemorySize, 33280);
    }

    cudaEventRecord(evFork, 0);
    cudaStreamWaitEvent(s2, evFork, 0);

    k_blk<<<1024, 256, 0, s2>>>(lv1);          // s2: DRAM-bound transpose

    k_tab<<<32, 256>>>(hix);                   // stream0: tiny table build
    cudaEventRecord(evTab, 0);
    cudaStreamWaitEvent(s2, evTab, 0);

    k_lv2<<<128, 1024, 65544>>>(lv2, out);     // stream0: LDS-bound gather

    k_lv1<<<512, 256, 33280, s2>>>(out + OUT_LV2_ELEMS);  // s2: L2-bound gather
    cudaEventRecord(evDone, s2);
    cudaStreamWaitEvent(0, evDone, 0);
}

// round 10
// speedup vs baseline: 1.0322x; 1.0322x over previous
#include <cuda_runtime.h>
#include <cuda_fp16.h>
#include <cstdint>

#define Hh 128
#define Ww 128
#define LL 16384          // H*W
#define NB 2
#define NC1 64
#define NC2 128
#define OUT_LV2_ELEMS 4194304
#define SENT 16384        // sentinel tap offset -> zero slot

// Scratch
__device__ unsigned short g_tab[NB * 9 * LL];                  // 576 KB tap offsets
__device__ uint2          g_blkh[(size_t)NB * (LL + 1) * 64];  // 16.8 MB half4 blocks

// ---------------------------------------------------------------------------
// k_tab: tap-offset table straight from hw (dtype sniff inline) + sentinel
// zeroing of g_blkh. 32 blocks, ~2us.
// ---------------------------------------------------------------------------
__global__ void k_tab(const int* __restrict__ hw) {
    __shared__ int s_or;
    int tid = threadIdx.x;
    if (tid == 0) s_or = 0;
    __syncthreads();
    int acc = 0;
#pragma unroll
    for (int k = 0; k < 8; k++) acc |= hw[2 * (tid + (k << 8)) + 1];
    if (acc) atomicOr(&s_or, 1);
    __syncthreads();
    int stride = s_or ? 1 : 2;                // int32 vs int64 source

    if (blockIdx.x == 0 && tid < 128) {       // zero sentinel cells
        int b = tid >> 6, c = tid & 63;
        g_blkh[((size_t)b * (LL + 1) + LL) * 64 + c] = make_uint2(0u, 0u);
    }

#pragma unroll
    for (int k = 0; k < 4; k++) {
        int gp = (blockIdx.x << 10) + (k << 8) + tid;   // 0..32767
        int b  = gp >> 14;
        int p  = gp & (LL - 1);
        int y = p >> 7, x = p & 127;
        unsigned short* tp = g_tab + (size_t)b * 9 * LL;
#pragma unroll
        for (int dy = -1; dy <= 1; dy++) {
#pragma unroll
            for (int dx = -1; dx <= 1; dx++) {
                int tap = (dy + 1) * 3 + (dx + 1);
                int oy = y - dy, ox = x - dx;
                unsigned short off = SENT;
                if ((unsigned)oy < Hh && (unsigned)ox < Ww) {
                    int m  = hw[((b << 14) + (oy << 7) + ox) * stride];
                    int sr = (m >> 7)  + dy;
                    int sc = (m & 127) + dx;
                    if ((unsigned)sr < Hh && (unsigned)sc < Ww)
                        off = (unsigned short)((sr << 7) + sc);
                }
                tp[tap * LL + p] = off;
            }
        }
    }
}

// ---------------------------------------------------------------------------
// k_blk: space-to-depth fp16 transpose of ONE batch of lv1 (512 blocks).
// ---------------------------------------------------------------------------
__global__ void k_blk(const float* __restrict__ lv1, int b) {
    __shared__ uint2 s2h[64 * 33];
    unsigned* sw = (unsigned*)s2h;
    int bid = blockIdx.x;                     // 512: (mh, vtile)
    int tid = threadIdx.x;
    int vt = bid & 3;
    int mh = (bid >> 2) & 127;
    int v0 = vt << 5;

#pragma unroll
    for (int k = 0; k < 8; k++) {
        int j  = tid + (k << 8);
        int c  = j >> 5;
        int dy = (j >> 4) & 1;
        int x4 = j & 15;
        const float4 val = *(const float4*)(lv1 + (((size_t)(b * NC1 + c)) << 16)
                                            + ((2 * mh + dy) << 8) + (v0 << 1) + (x4 << 2));
        int vl0 = x4 << 1;
        __half2 h0 = __floats2half2_rn(val.x, val.y);
        __half2 h1 = __floats2half2_rn(val.z, val.w);
        sw[(c * 33 + vl0    ) * 2 + dy] = *(unsigned*)&h0;
        sw[(c * 33 + vl0 + 1) * 2 + dy] = *(unsigned*)&h1;
    }
    __syncthreads();

    uint2* dst = g_blkh + ((size_t)b * (LL + 1) + (mh << 7) + v0) * 64;
#pragma unroll
    for (int k = 0; k < 8; k++) {
        int j  = tid + (k << 8);
        int vl = j >> 6;
        int c  = j & 63;
        dst[(size_t)vl * 64 + c] = s2h[c * 33 + vl];
    }
}

// ---------------------------------------------------------------------------
// k_lv2: plane-resident SMEM gather, 2 channels packed half2, 1024 threads.
// ---------------------------------------------------------------------------
__global__ void k_lv2(const float* __restrict__ lv2, float* __restrict__ out) {
    extern __shared__ unsigned s_plane[];            // 16385 half2
    int bcp = blockIdx.x;
    int cp  = bcp & 63;
    int b   = bcp >> 6;
    const float* base0 = lv2 + ((size_t)(b * NC2 + cp * 2) << 14);
    for (int i = threadIdx.x; i < LL; i += blockDim.x) {
        __half2 h = __floats2half2_rn(base0[i], base0[i + LL]);
        s_plane[i] = *(unsigned*)&h;
    }
    if (threadIdx.x == 0) s_plane[SENT] = 0u;
    __syncthreads();

    const unsigned short* tb = g_tab + (size_t)b * 9 * LL;
    float* out0 = out + ((size_t)(b * NC2 + cp * 2) << 14);
    const float inv9 = 1.0f / 9.0f;

#pragma unroll
    for (int it = 0; it < 8; it++) {
        int p1 = threadIdx.x + (it << 11);
        int p2 = p1 + 1024;
        float a0 = 0.f, a1 = 0.f, b0 = 0.f, b1 = 0.f;
#pragma unroll
        for (int tap = 0; tap < 9; tap++) {
            unsigned hv  = s_plane[tb[tap * LL + p1]];
            unsigned hw2 = s_plane[tb[tap * LL + p2]];
            float2 v = __half22float2(*(__half2*)&hv);
            float2 w = __half22float2(*(__half2*)&hw2);
            a0 += v.x; a1 += v.y;
            b0 += w.x; b1 += w.y;
        }
        out0[p1]      = a0 * inv9;
        out0[p1 + LL] = a1 * inv9;
        out0[p2]      = b0 * inv9;
        out0[p2 + LL] = b1 * inv9;
    }
}

// ---------------------------------------------------------------------------
// k_lv1: ONE batch (256 blocks). Warp-per-cell gather; lane = 2 channels;
// taps in groups of 5+4; half2 output staging (33.3KB, 4 blocks/SM).
// ---------------------------------------------------------------------------
__global__ void __launch_bounds__(256, 4) k_lv1(float* __restrict__ out, int b) {
    extern __shared__ __half2 shh[];          // 128 rows x 65 half2 = 33280 B
    int bid  = blockIdx.x;                    // 256: (u, vtile)
    int vt   = bid & 1;
    int u    = bid >> 1;
    int v0   = vt << 6;
    int w    = threadIdx.x >> 5;
    int lane = threadIdx.x & 31;
    const unsigned short* tb = g_tab + (size_t)b * 9 * LL;
    const uint4* blkb = (const uint4*)g_blkh + ((size_t)b * (LL + 1)) * 32 + lane;
    const float inv9 = 1.0f / 9.0f;

#pragma unroll
    for (int jj = 0; jj < 8; jj++) {
        int j = (w << 3) + jj;                // local cell 0..63
        int cell = (u << 7) + v0 + j;
        float4 A0 = make_float4(0.f, 0.f, 0.f, 0.f);   // channel 2*lane
        float4 A1 = make_float4(0.f, 0.f, 0.f, 0.f);   // channel 2*lane+1
        {   // taps 0..4
            uint4 t[5];
#pragma unroll
            for (int tap = 0; tap < 5; tap++)
                t[tap] = blkb[((size_t)tb[tap * LL + cell]) << 5];
#pragma unroll
            for (int tap = 0; tap < 5; tap++) {
                float2 f0 = __half22float2(*(__half2*)&t[tap].x);
                float2 f1 = __half22float2(*(__half2*)&t[tap].y);
                float2 f2 = __half22float2(*(__half2*)&t[tap].z);
                float2 f3 = __half22float2(*(__half2*)&t[tap].w);
                A0.x += f0.x; A0.y += f0.y; A0.z += f1.x; A0.w += f1.y;
                A1.x += f2.x; A1.y += f2.y; A1.z += f3.x; A1.w += f3.y;
            }
        }
        {   // taps 5..8
            uint4 t[4];
#pragma unroll
            for (int tap = 0; tap < 4; tap++)
                t[tap] = blkb[((size_t)tb[(5 + tap) * LL + cell]) << 5];
#pragma unroll
            for (int tap = 0; tap < 4; tap++) {
                float2 f0 = __half22float2(*(__half2*)&t[tap].x);
                float2 f1 = __half22float2(*(__half2*)&t[tap].y);
                float2 f2 = __half22float2(*(__half2*)&t[tap].z);
                float2 f3 = __half22float2(*(__half2*)&t[tap].w);
                A0.x += f0.x; A0.y += f0.y; A0.z += f1.x; A0.w += f1.y;
                A1.x += f2.x; A1.y += f2.y; A1.z += f3.x; A1.w += f3.y;
            }
        }
        int c0 = lane << 1;
        shh[(c0     ) * 65 + j] = __floats2half2_rn(A0.x * inv9, A0.y * inv9); // py0 c0
        shh[(64 + c0) * 65 + j] = __floats2half2_rn(A0.z * inv9, A0.w * inv9); // py1 c0
        shh[(c0 + 1 ) * 65 + j] = __floats2half2_rn(A1.x * inv9, A1.y * inv9); // py0 c0+1
        shh[(65 + c0) * 65 + j] = __floats2half2_rn(A1.z * inv9, A1.w * inv9); // py1 c0+1
    }
    __syncthreads();

    // Copy-out: warp per row (128 rows), half2->float2, coalesced 256B stores.
    for (int r = w; r < 128; r += 8) {
        int py = r >> 6;
        int c  = r & 63;
        float2* orow = (float2*)(out + (((size_t)(b * NC1 + c)) << 16)
                                 + ((2 * u + py) << 8) + (v0 << 1));
        const __half2* srow = shh + r * 65;
        orow[lane]      = __half22float2(srow[lane]);
        orow[lane + 32] = __half22float2(srow[lane + 32]);
    }
}

// ---------------------------------------------------------------------------
// Launch DAG (fork/join, capture-legal). Batch-split pipeline:
//   s0: tab -> evTab -> lv2 -> (wait evD2, evD3)
//   s2: (wait evFork) -> blk_b0 -> (wait evTab) -> lv1_b0 -> evD2
//   s3: (wait evFork) -> blk_b1 -> (wait evTab) -> lv1_b1 -> evD3
// ---------------------------------------------------------------------------
extern "C" void kernel_launch(void* const* d_in, const int* in_sizes, int n_in,
                              void* d_out, int out_size) {
    const float* lv1 = nullptr;   // 8388608
    const float* lv2 = nullptr;   // 4194304
    const int*   hix = nullptr;   // 32768
    for (int i = 0; i < n_in; i++) {
        if (in_sizes[i] == 8388608)      lv1 = (const float*)d_in[i];
        else if (in_sizes[i] == 4194304) lv2 = (const float*)d_in[i];
        else if (in_sizes[i] == 32768)   hix = (const int*)d_in[i];
    }
    float* out = (float*)d_out;
    float* out1 = out + OUT_LV2_ELEMS;

    static cudaStream_t s2 = nullptr, s3 = nullptr;
    static cudaEvent_t evFork = nullptr, evTab = nullptr, evD2 = nullptr, evD3 = nullptr;
    if (!s2) {
        cudaStreamCreateWithFlags(&s2, cudaStreamNonBlocking);
        cudaStreamCreateWithFlags(&s3, cudaStreamNonBlocking);
        cudaEventCreateWithFlags(&evFork, cudaEventDisableTiming);
        cudaEventCreateWithFlags(&evTab,  cudaEventDisableTiming);
        cudaEventCreateWithFlags(&evD2,   cudaEventDisableTiming);
        cudaEventCreateWithFlags(&evD3,   cudaEventDisableTiming);
        cudaFuncSetAttribute(k_lv2, cudaFuncAttributeMaxDynamicSharedMemorySize, 65544);
        cudaFuncSetAttribute(k_lv1, cudaFuncAttributeMaxDynamicSharedMemorySize, 33280);
    }

    cudaEventRecord(evFork, 0);
    cudaStreamWaitEvent(s2, evFork, 0);
    cudaStreamWaitEvent(s3, evFork, 0);

    k_blk<<<512, 256, 0, s2>>>(lv1, 0);        // s2: batch-0 transpose
    k_blk<<<512, 256, 0, s3>>>(lv1, 1);        // s3: batch-1 transpose

    k_tab<<<32, 256>>>(hix);                   // s0: tiny table build
    cudaEventRecord(evTab, 0);
    cudaStreamWaitEvent(s2, evTab, 0);
    cudaStreamWaitEvent(s3, evTab, 0);

    k_lv2<<<128, 1024, 65544>>>(lv2, out);     // s0: LDS-bound gather

    k_lv1<<<256, 256, 33280, s2>>>(out1, 0);   // s2: batch-0 gather
    k_lv1<<<256, 256, 33280, s3>>>(out1, 1);   // s3: batch-1 gather

    cudaEventRecord(evD2, s2);
    cudaEventRecord(evD3, s3);
    cudaStreamWaitEvent(0, evD2, 0);
    cudaStreamWaitEvent(0, evD3, 0);
}